// round 1
// baseline (speedup 1.0000x reference)
#include <cuda_runtime.h>
#include <math.h>

#define N_AA_C   300000
#define N_PROT_C 30000
#define D        128
#define DOUT     64
#define E_AP_MAX 300000
#define E_PP_MAX 960000
#define BATCH    16384
#define NEG      0.2f

// ---------------- device scratch (static; no runtime allocation) -------------
__device__ float g_xl_pp[N_PROT_C * D];
__device__ float g_xr_pp[BATCH * D];
__device__ float g_xr_ap[BATCH * D];
__device__ float g_hid[BATCH * D];

__device__ int g_cnt_ap[BATCH];
__device__ int g_cnt_pp[BATCH];
__device__ int g_off_ap[BATCH + 1];
__device__ int g_off_pp[BATCH + 1];
__device__ int g_cur_ap[BATCH];
__device__ int g_cur_pp[BATCH];
__device__ int g_src_ap[E_AP_MAX];
__device__ int g_src_pp[E_PP_MAX];

__device__ __forceinline__ float lrelu(float x) { return x > 0.f ? x : NEG * x; }

// ---------------- tiny utility kernels ---------------------------------------
__global__ void zero_kernel(int* p, int n) {
    int i = blockIdx.x * blockDim.x + threadIdx.x;
    if (i < n) p[i] = 0;
}

__global__ void hist_kernel(const int* __restrict__ dst, int E, int* __restrict__ cnt) {
    int e = blockIdx.x * blockDim.x + threadIdx.x;
    if (e < E) {
        int d = dst[e];
        if (d < BATCH) atomicAdd(&cnt[d], 1);
    }
}

// single-block exclusive scan of 16384 ints (1024 threads x 16)
__global__ void scan_kernel(const int* __restrict__ cnt, int* __restrict__ off,
                            int* __restrict__ cur) {
    __shared__ int s[1024];
    int t = threadIdx.x;
    int v[16];
    int run = 0;
#pragma unroll
    for (int i = 0; i < 16; i++) { v[i] = run; run += cnt[t * 16 + i]; }
    s[t] = run;
    __syncthreads();
    for (int d = 1; d < 1024; d <<= 1) {
        int add = (t >= d) ? s[t - d] : 0;
        __syncthreads();
        s[t] += add;
        __syncthreads();
    }
    int base = (t > 0) ? s[t - 1] : 0;
#pragma unroll
    for (int i = 0; i < 16; i++) {
        int o = base + v[i];
        off[t * 16 + i] = o;
        cur[t * 16 + i] = o;
    }
    if (t == 1023) off[16384] = s[1023];
}

__global__ void scatter_kernel(const int* __restrict__ ei, int E,
                               int* __restrict__ cur, int* __restrict__ out_src) {
    int e = blockIdx.x * blockDim.x + threadIdx.x;
    if (e < E) {
        int d = ei[E + e];
        if (d < BATCH) {
            int p = atomicAdd(&cur[d], 1);
            out_src[p] = ei[e];
        }
    }
}

// ---------------- Y[r,:] = X[r,:] @ W + b,  K=N=128 --------------------------
// block: 256 thr, 64 rows/block; thread: 8 rows x 4 cols; W + X tile in smem.
__global__ void __launch_bounds__(256) linear128_kernel(
    const float* __restrict__ X, const float* __restrict__ W,
    const float* __restrict__ b, float* __restrict__ Y, int nrows) {
    extern __shared__ float sm[];
    float4* Ws4 = (float4*)sm;            // 128*32 float4 = 64KB
    float4* Xs4 = (float4*)(sm + D * D);  // 64*32 float4  = 32KB
    int t = threadIdx.x;
    int lane = t & 31, ty = t >> 5;
    int row0 = blockIdx.x * 64;

    for (int i = t; i < D * D / 4; i += 256) Ws4[i] = ((const float4*)W)[i];
    for (int i = t; i < 64 * 32; i += 256) {
        int r = row0 + (i >> 5);
        Xs4[i] = (r < nrows) ? ((const float4*)X)[(size_t)r * 32 + (i & 31)]
                             : make_float4(0.f, 0.f, 0.f, 0.f);
    }
    __syncthreads();

    float4 bv = ((const float4*)b)[lane];
    float4 acc[8];
#pragma unroll
    for (int r = 0; r < 8; r++) acc[r] = bv;

    for (int k4 = 0; k4 < 32; k4++) {
        float4 w0 = Ws4[(4 * k4 + 0) * 32 + lane];
        float4 w1 = Ws4[(4 * k4 + 1) * 32 + lane];
        float4 w2 = Ws4[(4 * k4 + 2) * 32 + lane];
        float4 w3 = Ws4[(4 * k4 + 3) * 32 + lane];
#pragma unroll
        for (int r = 0; r < 8; r++) {
            float4 xv = Xs4[(ty * 8 + r) * 32 + k4];
            acc[r].x += xv.x * w0.x; acc[r].y += xv.x * w0.y; acc[r].z += xv.x * w0.z; acc[r].w += xv.x * w0.w;
            acc[r].x += xv.y * w1.x; acc[r].y += xv.y * w1.y; acc[r].z += xv.y * w1.z; acc[r].w += xv.y * w1.w;
            acc[r].x += xv.z * w2.x; acc[r].y += xv.z * w2.y; acc[r].z += xv.z * w2.z; acc[r].w += xv.z * w2.w;
            acc[r].x += xv.w * w3.x; acc[r].y += xv.w * w3.y; acc[r].z += xv.w * w3.z; acc[r].w += xv.w * w3.w;
        }
    }
#pragma unroll
    for (int r = 0; r < 8; r++) {
        int row = row0 + ty * 8 + r;
        if (row < nrows) ((float4*)Y)[(size_t)row * 32 + lane] = acc[r];
    }
}

// ---------------- AP: fused per-edge matvec + online segment softmax ---------
// warp per dst; edges sorted by dst; per group of 4 edges compute xl=x_aa@Wl+bl
// on the fly (W in smem), logit, online softmax, register accumulation.
__global__ void __launch_bounds__(256) ap_agg_kernel(
    const float* __restrict__ x_aa, const float* __restrict__ Wl,
    const float* __restrict__ bl, const float* __restrict__ att,
    const float* __restrict__ bias, const float* __restrict__ xr,
    const int* __restrict__ off, const int* __restrict__ srcs,
    float* __restrict__ hid) {
    extern __shared__ float sm[];
    float4* Ws4 = (float4*)sm;             // 128x128 W = 64KB
    float4* xsb = (float4*)(sm + D * D);   // 8 warps * 4 edges * 32 float4 = 16KB
    int t = threadIdx.x, lane = t & 31, warp = t >> 5;

    for (int i = t; i < D * D / 4; i += 256) Ws4[i] = ((const float4*)Wl)[i];
    __syncthreads();

    float4* xs = xsb + warp * (4 * 32);
    int dst = blockIdx.x * 8 + warp;
    float4 blv  = ((const float4*)bl)[lane];
    float4 attv = ((const float4*)att)[lane];
    float4 bsv  = ((const float4*)bias)[lane];
    float4 xrv  = ((const float4*)xr)[(size_t)dst * 32 + lane];

    float m = -INFINITY, denom = 0.f;
    float4 acc = make_float4(0.f, 0.f, 0.f, 0.f);
    int e0 = off[dst], e1 = off[dst + 1];

    for (int eb = e0; eb < e1; eb += 4) {
        int g = min(4, e1 - eb);
        int sl = (lane < g) ? srcs[eb + lane] : 0;
        __syncwarp();
#pragma unroll
        for (int i = 0; i < 4; i++) {
            if (i < g) {
                int s = __shfl_sync(0xffffffffu, sl, i);
                xs[i * 32 + lane] = ((const float4*)x_aa)[(size_t)s * 32 + lane];
            }
        }
        __syncwarp();

        float4 a[4];
#pragma unroll
        for (int i = 0; i < 4; i++) a[i] = blv;
        for (int k4 = 0; k4 < 32; k4++) {
            float4 w0 = Ws4[(4 * k4 + 0) * 32 + lane];
            float4 w1 = Ws4[(4 * k4 + 1) * 32 + lane];
            float4 w2 = Ws4[(4 * k4 + 2) * 32 + lane];
            float4 w3 = Ws4[(4 * k4 + 3) * 32 + lane];
#pragma unroll
            for (int i = 0; i < 4; i++) {
                if (i < g) {
                    float4 xv = xs[i * 32 + k4];
                    a[i].x += xv.x * w0.x; a[i].y += xv.x * w0.y; a[i].z += xv.x * w0.z; a[i].w += xv.x * w0.w;
                    a[i].x += xv.y * w1.x; a[i].y += xv.y * w1.y; a[i].z += xv.y * w1.z; a[i].w += xv.y * w1.w;
                    a[i].x += xv.z * w2.x; a[i].y += xv.z * w2.y; a[i].z += xv.z * w2.z; a[i].w += xv.z * w2.w;
                    a[i].x += xv.w * w3.x; a[i].y += xv.w * w3.y; a[i].z += xv.w * w3.z; a[i].w += xv.w * w3.w;
                }
            }
        }

        float lg[4];
#pragma unroll
        for (int i = 0; i < 4; i++) {
            if (i < g) {
                float e0v = lrelu(a[i].x + xrv.x);
                float e1v = lrelu(a[i].y + xrv.y);
                float e2v = lrelu(a[i].z + xrv.z);
                float e3v = lrelu(a[i].w + xrv.w);
                float p = e0v * attv.x + e1v * attv.y + e2v * attv.z + e3v * attv.w;
#pragma unroll
                for (int o = 16; o; o >>= 1) p += __shfl_xor_sync(0xffffffffu, p, o);
                lg[i] = p;
            }
        }
        float gm = m;
#pragma unroll
        for (int i = 0; i < 4; i++) if (i < g) gm = fmaxf(gm, lg[i]);
        float sc = __expf(m - gm);
        denom *= sc; acc.x *= sc; acc.y *= sc; acc.z *= sc; acc.w *= sc;
#pragma unroll
        for (int i = 0; i < 4; i++) {
            if (i < g) {
                float w = __expf(lg[i] - gm);
                denom += w;
                acc.x += w * a[i].x; acc.y += w * a[i].y;
                acc.z += w * a[i].z; acc.w += w * a[i].w;
            }
        }
        m = gm;
    }

    float inv = (denom > 0.f) ? 1.f / denom : 0.f;
    float4 o;
    o.x = acc.x * inv + bsv.x; o.y = acc.y * inv + bsv.y;
    o.z = acc.z * inv + bsv.z; o.w = acc.w * inv + bsv.w;
    ((float4*)hid)[(size_t)dst * 32 + lane] = o;
}

// ---------------- PP: gather precomputed xl rows + online softmax ------------
__global__ void __launch_bounds__(256) pp_agg_kernel(
    const float* __restrict__ xl, const float* __restrict__ xr,
    const float* __restrict__ att, const float* __restrict__ bias,
    const int* __restrict__ off, const int* __restrict__ srcs,
    float* __restrict__ hid) {
    int t = threadIdx.x, lane = t & 31, warp = t >> 5;
    int dst = blockIdx.x * 8 + warp;
    float4 attv = ((const float4*)att)[lane];
    float4 bsv  = ((const float4*)bias)[lane];
    float4 xrv  = ((const float4*)xr)[(size_t)dst * 32 + lane];

    float m = -INFINITY, denom = 0.f;
    float4 acc = make_float4(0.f, 0.f, 0.f, 0.f);
    int e0 = off[dst], e1 = off[dst + 1];

    for (int eb = e0; eb < e1; eb += 4) {
        int g = min(4, e1 - eb);
        int sl = (lane < g) ? srcs[eb + lane] : 0;
        float4 xv[4];
        float lg[4];
#pragma unroll
        for (int i = 0; i < 4; i++) {
            if (i < g) {
                int s = __shfl_sync(0xffffffffu, sl, i);
                xv[i] = ((const float4*)xl)[(size_t)s * 32 + lane];
            }
        }
#pragma unroll
        for (int i = 0; i < 4; i++) {
            if (i < g) {
                float e0v = lrelu(xv[i].x + xrv.x);
                float e1v = lrelu(xv[i].y + xrv.y);
                float e2v = lrelu(xv[i].z + xrv.z);
                float e3v = lrelu(xv[i].w + xrv.w);
                float p = e0v * attv.x + e1v * attv.y + e2v * attv.z + e3v * attv.w;
#pragma unroll
                for (int o = 16; o; o >>= 1) p += __shfl_xor_sync(0xffffffffu, p, o);
                lg[i] = p;
            }
        }
        float gm = m;
#pragma unroll
        for (int i = 0; i < 4; i++) if (i < g) gm = fmaxf(gm, lg[i]);
        float sc = __expf(m - gm);
        denom *= sc; acc.x *= sc; acc.y *= sc; acc.z *= sc; acc.w *= sc;
#pragma unroll
        for (int i = 0; i < 4; i++) {
            if (i < g) {
                float w = __expf(lg[i] - gm);
                denom += w;
                acc.x += w * xv[i].x; acc.y += w * xv[i].y;
                acc.z += w * xv[i].z; acc.w += w * xv[i].w;
            }
        }
        m = gm;
    }

    float inv = (denom > 0.f) ? 1.f / denom : 0.f;
    float4 h = ((float4*)hid)[(size_t)dst * 32 + lane];
    h.x += acc.x * inv + bsv.x; h.y += acc.y * inv + bsv.y;
    h.z += acc.z * inv + bsv.z; h.w += acc.w * inv + bsv.w;
    ((float4*)hid)[(size_t)dst * 32 + lane] = h;
}

// ---------------- out = relu(hid) @ W_lin + b_lin  (128 -> 64) ---------------
// block: 256 thr = 8 warps, 4 rows per warp; W_lin + staged rows in smem.
__global__ void __launch_bounds__(256) final_kernel(
    const float* __restrict__ hid, const float* __restrict__ Wl,
    const float* __restrict__ bl, float* __restrict__ out) {
    extern __shared__ float sm[];
    float* Ws = sm;              // 128*64 = 32KB
    float* hs = sm + D * DOUT;   // 32*128 = 16KB
    int t = threadIdx.x, lane = t & 31, warp = t >> 5;

    for (int i = t; i < D * DOUT / 4; i += 256) ((float4*)Ws)[i] = ((const float4*)Wl)[i];

    int row0 = blockIdx.x * 32 + warp * 4;
#pragma unroll
    for (int r = 0; r < 4; r++) {
        float4 h = ((const float4*)hid)[(size_t)(row0 + r) * 32 + lane];
        h.x = fmaxf(h.x, 0.f); h.y = fmaxf(h.y, 0.f);
        h.z = fmaxf(h.z, 0.f); h.w = fmaxf(h.w, 0.f);
        ((float4*)&hs[(warp * 4 + r) * D])[lane] = h;
    }
    __syncthreads();

    float b0 = bl[lane], b1 = bl[lane + 32];
    float acc0[4], acc1[4];
#pragma unroll
    for (int r = 0; r < 4; r++) { acc0[r] = b0; acc1[r] = b1; }

    for (int k = 0; k < D; k++) {
        float w0 = Ws[k * DOUT + lane];
        float w1 = Ws[k * DOUT + lane + 32];
#pragma unroll
        for (int r = 0; r < 4; r++) {
            float h = hs[(warp * 4 + r) * D + k];
            acc0[r] += h * w0;
            acc1[r] += h * w1;
        }
    }
#pragma unroll
    for (int r = 0; r < 4; r++) {
        int row = row0 + r;
        out[(size_t)row * DOUT + lane] = acc0[r];
        out[(size_t)row * DOUT + lane + 32] = acc1[r];
    }
}

// ---------------- launch ------------------------------------------------------
extern "C" void kernel_launch(void* const* d_in, const int* in_sizes, int n_in,
                              void* d_out, int out_size) {
    const float* x_aa    = (const float*)d_in[0];
    const float* x_prot  = (const float*)d_in[1];
    const int*   ei_ap   = (const int*)d_in[2];
    const int*   ei_pp   = (const int*)d_in[3];
    // d_in[4] = batch_size (compile-time BATCH)
    const float* Wl_ap   = (const float*)d_in[5];
    const float* bl_ap   = (const float*)d_in[6];
    const float* Wr_ap   = (const float*)d_in[7];
    const float* br_ap   = (const float*)d_in[8];
    const float* att_ap  = (const float*)d_in[9];
    const float* bias_ap = (const float*)d_in[10];
    const float* Wl_pp   = (const float*)d_in[11];
    const float* bl_pp   = (const float*)d_in[12];
    const float* Wr_pp   = (const float*)d_in[13];
    const float* br_pp   = (const float*)d_in[14];
    const float* att_pp  = (const float*)d_in[15];
    const float* bias_pp = (const float*)d_in[16];
    const float* W_lin   = (const float*)d_in[17];
    const float* b_lin   = (const float*)d_in[18];
    float* out = (float*)d_out;

    int E_ap = in_sizes[2] / 2;
    int E_pp = in_sizes[3] / 2;

    void* p;
    cudaGetSymbolAddress(&p, g_xl_pp);  float* xl_pp = (float*)p;
    cudaGetSymbolAddress(&p, g_xr_pp);  float* xr_pp = (float*)p;
    cudaGetSymbolAddress(&p, g_xr_ap);  float* xr_ap = (float*)p;
    cudaGetSymbolAddress(&p, g_hid);    float* hid   = (float*)p;
    cudaGetSymbolAddress(&p, g_cnt_ap); int* cnt_ap = (int*)p;
    cudaGetSymbolAddress(&p, g_cnt_pp); int* cnt_pp = (int*)p;
    cudaGetSymbolAddress(&p, g_off_ap); int* off_ap = (int*)p;
    cudaGetSymbolAddress(&p, g_off_pp); int* off_pp = (int*)p;
    cudaGetSymbolAddress(&p, g_cur_ap); int* cur_ap = (int*)p;
    cudaGetSymbolAddress(&p, g_cur_pp); int* cur_pp = (int*)p;
    cudaGetSymbolAddress(&p, g_src_ap); int* src_ap = (int*)p;
    cudaGetSymbolAddress(&p, g_src_pp); int* src_pp = (int*)p;

    cudaFuncSetAttribute(linear128_kernel, cudaFuncAttributeMaxDynamicSharedMemorySize, 98304);
    cudaFuncSetAttribute(ap_agg_kernel,    cudaFuncAttributeMaxDynamicSharedMemorySize, 81920);
    cudaFuncSetAttribute(final_kernel,     cudaFuncAttributeMaxDynamicSharedMemorySize, 49152);

    // build dst-sorted edge lists (only dst < BATCH)
    zero_kernel<<<(BATCH + 255) / 256, 256>>>(cnt_ap, BATCH);
    zero_kernel<<<(BATCH + 255) / 256, 256>>>(cnt_pp, BATCH);
    hist_kernel<<<(E_ap + 255) / 256, 256>>>(ei_ap + E_ap, E_ap, cnt_ap);
    hist_kernel<<<(E_pp + 255) / 256, 256>>>(ei_pp + E_pp, E_pp, cnt_pp);
    scan_kernel<<<1, 1024>>>(cnt_ap, off_ap, cur_ap);
    scan_kernel<<<1, 1024>>>(cnt_pp, off_pp, cur_pp);
    scatter_kernel<<<(E_ap + 255) / 256, 256>>>(ei_ap, E_ap, cur_ap, src_ap);
    scatter_kernel<<<(E_pp + 255) / 256, 256>>>(ei_pp, E_pp, cur_pp, src_pp);

    // node-level linear transforms (only rows that are ever read)
    linear128_kernel<<<(N_PROT_C + 63) / 64, 256, 98304>>>(x_prot, Wl_pp, bl_pp, xl_pp, N_PROT_C);
    linear128_kernel<<<BATCH / 64, 256, 98304>>>(x_prot, Wr_pp, br_pp, xr_pp, BATCH);
    linear128_kernel<<<BATCH / 64, 256, 98304>>>(x_prot, Wr_ap, br_ap, xr_ap, BATCH);

    // fused GATv2 aggregations (warp per destination, online softmax)
    ap_agg_kernel<<<BATCH / 8, 256, 81920>>>(x_aa, Wl_ap, bl_ap, att_ap, bias_ap,
                                             xr_ap, off_ap, src_ap, hid);
    pp_agg_kernel<<<BATCH / 8, 256>>>(xl_pp, xr_pp, att_pp, bias_pp,
                                      off_pp, src_pp, hid);

    // relu + final linear
    final_kernel<<<BATCH / 32, 256, 49152>>>(hid, W_lin, b_lin, out);
}

// round 2
// speedup vs baseline: 1.4080x; 1.4080x over previous
#include <cuda_runtime.h>
#include <math.h>

#define N_AA_C   300000
#define N_PROT_C 30000
#define D        128
#define DOUT     64
#define E_AP_MAX 300000
#define E_PP_MAX 960000
#define BATCH    16384
#define NEG      0.2f

// ---------------- device scratch (static; no runtime allocation) -------------
__device__ float g_xl_pp[N_PROT_C * D];        // 15.4 MB
__device__ float g_xr_pp[BATCH * D];
__device__ float g_xr_ap[BATCH * D];
__device__ float g_hid[BATCH * D];
__device__ float g_xl_e[(size_t)E_AP_MAX * D]; // 153.6 MB: per-AP-edge xl rows

__device__ int g_cnt_ap[BATCH];
__device__ int g_cnt_pp[BATCH];
__device__ int g_off_ap[BATCH + 1];
__device__ int g_off_pp[BATCH + 1];
__device__ int g_cur_ap[BATCH];
__device__ int g_cur_pp[BATCH];
__device__ int g_src_ap[E_AP_MAX];
__device__ int g_src_pp[E_PP_MAX];

__device__ __forceinline__ float lrelu(float x) { return x > 0.f ? x : NEG * x; }

// packed f32x2 helpers (Blackwell FFMA2 — only reachable via PTX)
__device__ __forceinline__ unsigned long long splat2(float x) {
    unsigned long long d;
    asm("mov.b64 %0, {%1, %1};" : "=l"(d) : "r"(__float_as_uint(x)));
    return d;
}
__device__ __forceinline__ unsigned long long ffma2(
    unsigned long long a, unsigned long long b, unsigned long long c) {
    unsigned long long d;
    asm("fma.rn.f32x2 %0, %1, %2, %3;" : "=l"(d) : "l"(a), "l"(b), "l"(c));
    return d;
}

// ---------------- fused preprocessing kernels --------------------------------
__global__ void zero2_kernel(int* a, int* b) {
    int i = blockIdx.x * blockDim.x + threadIdx.x;
    if (i < BATCH) a[i] = 0;
    else if (i < 2 * BATCH) b[i - BATCH] = 0;
}

__global__ void hist2_kernel(const int* __restrict__ ei_ap, int E_ap, int* __restrict__ cnt_ap,
                             const int* __restrict__ ei_pp, int E_pp, int* __restrict__ cnt_pp) {
    int i = blockIdx.x * blockDim.x + threadIdx.x;
    if (i < E_ap) {
        int d = ei_ap[E_ap + i];
        if (d < BATCH) atomicAdd(&cnt_ap[d], 1);
    } else if (i < E_ap + E_pp) {
        int j = i - E_ap;
        int d = ei_pp[E_pp + j];
        if (d < BATCH) atomicAdd(&cnt_pp[d], 1);
    }
}

// grid=2: block 0 scans ap, block 1 scans pp. 1024 threads x 16 elems.
__global__ void scan2_kernel(const int* __restrict__ cnt_ap, int* __restrict__ off_ap, int* __restrict__ cur_ap,
                             const int* __restrict__ cnt_pp, int* __restrict__ off_pp, int* __restrict__ cur_pp) {
    const int* cnt = blockIdx.x ? cnt_pp : cnt_ap;
    int* off = blockIdx.x ? off_pp : off_ap;
    int* cur = blockIdx.x ? cur_pp : cur_ap;
    __shared__ int s[1024];
    int t = threadIdx.x;
    int v[16];
    int run = 0;
#pragma unroll
    for (int i = 0; i < 16; i++) { v[i] = run; run += cnt[t * 16 + i]; }
    s[t] = run;
    __syncthreads();
    for (int d = 1; d < 1024; d <<= 1) {
        int add = (t >= d) ? s[t - d] : 0;
        __syncthreads();
        s[t] += add;
        __syncthreads();
    }
    int base = (t > 0) ? s[t - 1] : 0;
#pragma unroll
    for (int i = 0; i < 16; i++) {
        int o = base + v[i];
        off[t * 16 + i] = o;
        cur[t * 16 + i] = o;
    }
    if (t == 1023) off[16384] = s[1023];
}

__global__ void scatter2_kernel(const int* __restrict__ ei_ap, int E_ap, int* __restrict__ cur_ap, int* __restrict__ src_ap,
                                const int* __restrict__ ei_pp, int E_pp, int* __restrict__ cur_pp, int* __restrict__ src_pp) {
    int i = blockIdx.x * blockDim.x + threadIdx.x;
    if (i < E_ap) {
        int d = ei_ap[E_ap + i];
        if (d < BATCH) {
            int p = atomicAdd(&cur_ap[d], 1);
            src_ap[p] = ei_ap[i];
        }
    } else if (i < E_ap + E_pp) {
        int j = i - E_ap;
        int d = ei_pp[E_pp + j];
        if (d < BATCH) {
            int p = atomicAdd(&cur_pp[d], 1);
            src_pp[p] = ei_pp[j];
        }
    }
}

// ---------------- Y[r,:] = X[rows[r],:] @ W + b,  K=N=128, FFMA2 -------------
// block: 256 thr, 64 rows/block; thread: 8 rows x 4 cols (packed as 2x f32x2).
template <bool GATHER>
__global__ void __launch_bounds__(256) gemm128_kernel(
    const float* __restrict__ X, const float* __restrict__ W,
    const float* __restrict__ b, float* __restrict__ Y, int nrows_const,
    const int* __restrict__ srcs, const int* __restrict__ total_ptr) {
    int total = GATHER ? *total_ptr : nrows_const;
    int row0 = blockIdx.x * 64;
    if (row0 >= total) return;

    extern __shared__ float sm[];
    float4* Ws4 = (float4*)sm;            // 128*32 float4 = 64KB
    float4* Xs4 = (float4*)(sm + D * D);  // 64*32 float4  = 32KB
    const ulonglong2* Wsu = (const ulonglong2*)sm;
    int t = threadIdx.x;
    int lane = t & 31, ty = t >> 5;

    for (int i = t; i < D * D / 4; i += 256) Ws4[i] = ((const float4*)W)[i];
    for (int i = t; i < 64 * 32; i += 256) {
        int r = row0 + (i >> 5);
        int rr = 0;
        if (r < total) rr = GATHER ? srcs[r] : r;
        Xs4[i] = ((const float4*)X)[(size_t)rr * 32 + (i & 31)];
    }
    __syncthreads();

    float4 bv = ((const float4*)b)[lane];
    ulonglong2 bvu = *reinterpret_cast<ulonglong2*>(&bv);
    unsigned long long alo[8], ahi[8];
#pragma unroll
    for (int r = 0; r < 8; r++) { alo[r] = bvu.x; ahi[r] = bvu.y; }

    for (int k4 = 0; k4 < 32; k4++) {
        ulonglong2 w0 = Wsu[(4 * k4 + 0) * 32 + lane];
        ulonglong2 w1 = Wsu[(4 * k4 + 1) * 32 + lane];
        ulonglong2 w2 = Wsu[(4 * k4 + 2) * 32 + lane];
        ulonglong2 w3 = Wsu[(4 * k4 + 3) * 32 + lane];
#pragma unroll
        for (int r = 0; r < 8; r++) {
            float4 xv = Xs4[(ty * 8 + r) * 32 + k4];
            unsigned long long s0 = splat2(xv.x);
            unsigned long long s1 = splat2(xv.y);
            unsigned long long s2 = splat2(xv.z);
            unsigned long long s3 = splat2(xv.w);
            alo[r] = ffma2(s0, w0.x, alo[r]); ahi[r] = ffma2(s0, w0.y, ahi[r]);
            alo[r] = ffma2(s1, w1.x, alo[r]); ahi[r] = ffma2(s1, w1.y, ahi[r]);
            alo[r] = ffma2(s2, w2.x, alo[r]); ahi[r] = ffma2(s2, w2.y, ahi[r]);
            alo[r] = ffma2(s3, w3.x, alo[r]); ahi[r] = ffma2(s3, w3.y, ahi[r]);
        }
    }
#pragma unroll
    for (int r = 0; r < 8; r++) {
        int row = row0 + ty * 8 + r;
        if (row < total) {
            ulonglong2 o; o.x = alo[r]; o.y = ahi[r];
            ((ulonglong2*)Y)[(size_t)row * 32 + lane] = o;
        }
    }
}

// ---------------- per-dst online segment softmax over xl rows ----------------
// GATHER: rows indexed via srcs[e] (PP). !GATHER: row = e (AP, sequential).
template <bool GATHER>
__device__ __forceinline__ float4 seg_softmax(
    const float* __restrict__ xl, const int* __restrict__ srcs,
    int e0, int e1, float4 xrv, float4 attv, int lane) {
    float m = -INFINITY, denom = 0.f;
    float4 acc = make_float4(0.f, 0.f, 0.f, 0.f);

    for (int eb = e0; eb < e1; eb += 4) {
        int g = min(4, e1 - eb);
        int sl = 0;
        if (GATHER) sl = (lane < g) ? srcs[eb + lane] : 0;
        float4 xv[4];
        float lg[4];
#pragma unroll
        for (int i = 0; i < 4; i++) {
            if (i < g) {
                int row = GATHER ? __shfl_sync(0xffffffffu, sl, i) : (eb + i);
                xv[i] = ((const float4*)xl)[(size_t)row * 32 + lane];
            }
        }
#pragma unroll
        for (int i = 0; i < 4; i++) {
            if (i < g) {
                float p = lrelu(xv[i].x + xrv.x) * attv.x
                        + lrelu(xv[i].y + xrv.y) * attv.y
                        + lrelu(xv[i].z + xrv.z) * attv.z
                        + lrelu(xv[i].w + xrv.w) * attv.w;
#pragma unroll
                for (int o = 16; o; o >>= 1) p += __shfl_xor_sync(0xffffffffu, p, o);
                lg[i] = p;
            }
        }
        float gm = m;
#pragma unroll
        for (int i = 0; i < 4; i++) if (i < g) gm = fmaxf(gm, lg[i]);
        float sc = __expf(m - gm);
        denom *= sc; acc.x *= sc; acc.y *= sc; acc.z *= sc; acc.w *= sc;
#pragma unroll
        for (int i = 0; i < 4; i++) {
            if (i < g) {
                float w = __expf(lg[i] - gm);
                denom += w;
                acc.x += w * xv[i].x; acc.y += w * xv[i].y;
                acc.z += w * xv[i].z; acc.w += w * xv[i].w;
            }
        }
        m = gm;
    }
    float inv = (denom > 0.f) ? 1.f / denom : 0.f;
    acc.x *= inv; acc.y *= inv; acc.z *= inv; acc.w *= inv;
    return acc;
}

// warp per dst; computes AP (sequential edge rows) + PP (gathered rows), writes sum
__global__ void __launch_bounds__(256) agg_kernel(
    const float* __restrict__ xl_e, const float* __restrict__ xr_ap,
    const float* __restrict__ att_ap, const float* __restrict__ bias_ap,
    const int* __restrict__ off_ap,
    const float* __restrict__ xl_pp, const float* __restrict__ xr_pp,
    const float* __restrict__ att_pp, const float* __restrict__ bias_pp,
    const int* __restrict__ off_pp, const int* __restrict__ src_pp,
    float* __restrict__ hid) {
    int t = threadIdx.x, lane = t & 31, warp = t >> 5;
    int dst = blockIdx.x * 8 + warp;

    float4 attv_a = ((const float4*)att_ap)[lane];
    float4 bsv_a  = ((const float4*)bias_ap)[lane];
    float4 xrv_a  = ((const float4*)xr_ap)[(size_t)dst * 32 + lane];
    float4 ap = seg_softmax<false>(xl_e, nullptr, off_ap[dst], off_ap[dst + 1],
                                   xrv_a, attv_a, lane);

    float4 attv_p = ((const float4*)att_pp)[lane];
    float4 bsv_p  = ((const float4*)bias_pp)[lane];
    float4 xrv_p  = ((const float4*)xr_pp)[(size_t)dst * 32 + lane];
    float4 pp = seg_softmax<true>(xl_pp, src_pp, off_pp[dst], off_pp[dst + 1],
                                  xrv_p, attv_p, lane);

    float4 o;
    o.x = ap.x + bsv_a.x + pp.x + bsv_p.x;
    o.y = ap.y + bsv_a.y + pp.y + bsv_p.y;
    o.z = ap.z + bsv_a.z + pp.z + bsv_p.z;
    o.w = ap.w + bsv_a.w + pp.w + bsv_p.w;
    ((float4*)hid)[(size_t)dst * 32 + lane] = o;
}

// ---------------- out = relu(hid) @ W_lin + b_lin  (128 -> 64) ---------------
__global__ void __launch_bounds__(256) final_kernel(
    const float* __restrict__ hid, const float* __restrict__ Wl,
    const float* __restrict__ bl, float* __restrict__ out) {
    extern __shared__ float sm[];
    float* Ws = sm;              // 128*64 = 32KB
    float* hs = sm + D * DOUT;   // 32*128 = 16KB
    int t = threadIdx.x, lane = t & 31, warp = t >> 5;

    for (int i = t; i < D * DOUT / 4; i += 256) ((float4*)Ws)[i] = ((const float4*)Wl)[i];

    int row0 = blockIdx.x * 32 + warp * 4;
#pragma unroll
    for (int r = 0; r < 4; r++) {
        float4 h = ((const float4*)hid)[(size_t)(row0 + r) * 32 + lane];
        h.x = fmaxf(h.x, 0.f); h.y = fmaxf(h.y, 0.f);
        h.z = fmaxf(h.z, 0.f); h.w = fmaxf(h.w, 0.f);
        ((float4*)&hs[(warp * 4 + r) * D])[lane] = h;
    }
    __syncthreads();

    float b0 = bl[lane], b1 = bl[lane + 32];
    float acc0[4], acc1[4];
#pragma unroll
    for (int r = 0; r < 4; r++) { acc0[r] = b0; acc1[r] = b1; }

    for (int k = 0; k < D; k++) {
        float w0 = Ws[k * DOUT + lane];
        float w1 = Ws[k * DOUT + lane + 32];
#pragma unroll
        for (int r = 0; r < 4; r++) {
            float h = hs[(warp * 4 + r) * D + k];
            acc0[r] += h * w0;
            acc1[r] += h * w1;
        }
    }
#pragma unroll
    for (int r = 0; r < 4; r++) {
        int row = row0 + r;
        out[(size_t)row * DOUT + lane] = acc0[r];
        out[(size_t)row * DOUT + lane + 32] = acc1[r];
    }
}

// ---------------- launch ------------------------------------------------------
extern "C" void kernel_launch(void* const* d_in, const int* in_sizes, int n_in,
                              void* d_out, int out_size) {
    const float* x_aa    = (const float*)d_in[0];
    const float* x_prot  = (const float*)d_in[1];
    const int*   ei_ap   = (const int*)d_in[2];
    const int*   ei_pp   = (const int*)d_in[3];
    const float* Wl_ap   = (const float*)d_in[5];
    const float* bl_ap   = (const float*)d_in[6];
    const float* Wr_ap   = (const float*)d_in[7];
    const float* br_ap   = (const float*)d_in[8];
    const float* att_ap  = (const float*)d_in[9];
    const float* bias_ap = (const float*)d_in[10];
    const float* Wl_pp   = (const float*)d_in[11];
    const float* bl_pp   = (const float*)d_in[12];
    const float* Wr_pp   = (const float*)d_in[13];
    const float* br_pp   = (const float*)d_in[14];
    const float* att_pp  = (const float*)d_in[15];
    const float* bias_pp = (const float*)d_in[16];
    const float* W_lin   = (const float*)d_in[17];
    const float* b_lin   = (const float*)d_in[18];
    float* out = (float*)d_out;

    int E_ap = in_sizes[2] / 2;
    int E_pp = in_sizes[3] / 2;

    void* p;
    cudaGetSymbolAddress(&p, g_xl_pp);  float* xl_pp = (float*)p;
    cudaGetSymbolAddress(&p, g_xr_pp);  float* xr_pp = (float*)p;
    cudaGetSymbolAddress(&p, g_xr_ap);  float* xr_ap = (float*)p;
    cudaGetSymbolAddress(&p, g_hid);    float* hid   = (float*)p;
    cudaGetSymbolAddress(&p, g_xl_e);   float* xl_e  = (float*)p;
    cudaGetSymbolAddress(&p, g_cnt_ap); int* cnt_ap = (int*)p;
    cudaGetSymbolAddress(&p, g_cnt_pp); int* cnt_pp = (int*)p;
    cudaGetSymbolAddress(&p, g_off_ap); int* off_ap = (int*)p;
    cudaGetSymbolAddress(&p, g_off_pp); int* off_pp = (int*)p;
    cudaGetSymbolAddress(&p, g_cur_ap); int* cur_ap = (int*)p;
    cudaGetSymbolAddress(&p, g_cur_pp); int* cur_pp = (int*)p;
    cudaGetSymbolAddress(&p, g_src_ap); int* src_ap = (int*)p;
    cudaGetSymbolAddress(&p, g_src_pp); int* src_pp = (int*)p;

    cudaFuncSetAttribute(gemm128_kernel<false>, cudaFuncAttributeMaxDynamicSharedMemorySize, 98304);
    cudaFuncSetAttribute(gemm128_kernel<true>,  cudaFuncAttributeMaxDynamicSharedMemorySize, 98304);
    cudaFuncSetAttribute(final_kernel,          cudaFuncAttributeMaxDynamicSharedMemorySize, 49152);

    int E_both = E_ap + E_pp;

    // 0: zero both histograms
    zero2_kernel<<<(2 * BATCH + 255) / 256, 256>>>(cnt_ap, cnt_pp);
    // 1: histogram both edge lists (dst < BATCH only)
    hist2_kernel<<<(E_both + 255) / 256, 256>>>(ei_ap, E_ap, cnt_ap, ei_pp, E_pp, cnt_pp);
    // 2: exclusive scans (one block each)
    scan2_kernel<<<2, 1024>>>(cnt_ap, off_ap, cur_ap, cnt_pp, off_pp, cur_pp);
    // 3: heavy GEMM in the profiled slot: xl_pp = x_prot @ Wl_pp + bl_pp (30000 rows)
    gemm128_kernel<false><<<(N_PROT_C + 63) / 64, 256, 98304>>>(
        x_prot, Wl_pp, bl_pp, xl_pp, N_PROT_C, nullptr, nullptr);
    // 4: scatter src indices into dst-sorted order
    scatter2_kernel<<<(E_both + 255) / 256, 256>>>(ei_ap, E_ap, cur_ap, src_ap,
                                                   ei_pp, E_pp, cur_pp, src_pp);
    // 5,6: xr transforms for the batch rows
    gemm128_kernel<false><<<BATCH / 64, 256, 98304>>>(
        x_prot, Wr_pp, br_pp, xr_pp, BATCH, nullptr, nullptr);
    gemm128_kernel<false><<<BATCH / 64, 256, 98304>>>(
        x_prot, Wr_ap, br_ap, xr_ap, BATCH, nullptr, nullptr);
    // 7: per-AP-edge xl rows via gathered GEMM (dst-sorted edge order)
    gemm128_kernel<true><<<(E_AP_MAX + 63) / 64, 256, 98304>>>(
        x_aa, Wl_ap, bl_ap, xl_e, 0, src_ap, &off_ap[BATCH]);
    // 8: fused AP+PP segment softmax aggregation (warp per dst)
    agg_kernel<<<BATCH / 8, 256>>>(xl_e, xr_ap, att_ap, bias_ap, off_ap,
                                   xl_pp, xr_pp, att_pp, bias_pp, off_pp, src_pp, hid);
    // 9: relu + final linear
    final_kernel<<<BATCH / 32, 256, 49152>>>(hid, W_lin, b_lin, out);
}